// round 14
// baseline (speedup 1.0000x reference)
#include <cuda_runtime.h>
#include <cuda_bf16.h>

// Problem constants (fixed shapes)
#define BATCH 4
#define CIN   64
#define HNUM  96
#define WNUM  96
#define G     8
#define OG    8
#define OGH   4            // channels handled per block
#define IG    8
#define KW    7
#define PAD   3
#define PLANE (HNUM * WNUM)

// Tiling: 192 threads = 16 rows x 12... -> 16 px-rows, 16 thread-cols? Use
// 192 = 16 rows x 12 cols is awkward; keep 2px/thread: 16 rows x 16 cols needs
// 256. Instead: 192 threads, each owns 2 px; tile 16x24? Grid must divide 96.
// Choose tile TH=16, TW=24: 16*12=192 threads (12 thread-cols x 2px = 24 wide).
#define TH 16
#define TW 24
#define TCN 12
#define NTHREADS 192
#define HH  (TH + KW - 1)   // 22
#define HWD (TW + KW - 1)   // 30
#define KVSTR 60            // floats per row: 30 px * 2 (k,v). 240B, 16B-aligned.

__device__ __forceinline__ float ex2f(float l) {
    float e;
    asm("ex2.approx.f32 %0, %1;" : "=f"(e) : "f"(l));
    return e;
}

__global__ __launch_bounds__(NTHREADS, 8)
void attn_fused_kernel(const float* __restrict__ x,
                       const float* __restrict__ wq,
                       const float* __restrict__ wk,
                       const float* __restrict__ wv,
                       const float* __restrict__ h_emb,
                       const float* __restrict__ w_emb,
                       float* __restrict__ out)
{
    // k,v interleaved per pixel for LDS.128: [ch][row][2*col + {k,v}]
    __shared__ __align__(16) float kv_s[OGH][HH][KVSTR];   // 4*22*60*4 = 20.6 KB
    __shared__ float  wq_s[OGH * IG];
    __shared__ float2 wkv_s[OGH * IG];
    __shared__ float  emb_s[OGH * KW];

    const int tid  = threadIdx.x;
    const int bz   = blockIdx.z;       // ((b*8+g)*2 + half)
    const int half_ = bz & 1;
    const int g    = (bz >> 1) & 7;
    const int b    = bz >> 4;
    const int h0   = blockIdx.y * TH;
    const int w0   = blockIdx.x * TW;

    if (tid < 32) {
        const int wi = g * 64 + half_ * 32 + tid;
        wq_s[tid]  = wq[wi];
        wkv_s[tid] = make_float2(wk[wi], wv[wi]);
    } else if (tid >= 32 && tid < 60) {
        const float* ep = half_ ? w_emb : h_emb;
        emb_s[tid - 32] = ep[g * 28 + (tid - 32)];
    }
    __syncthreads();

    const float* xg = x + (size_t)(b * CIN + g * IG) * PLANE;
    const int cbase = half_ * OGH;

    // --- phase 1: grouped 1x1 conv k,v over haloed tile -> interleaved SMEM ---
    for (int p = tid; p < HH * HWD; p += NTHREADS) {
        const int yy = p / HWD;
        const int xx = p - yy * HWD;
        const int gy = h0 + yy - PAD;
        const int gx = w0 + xx - PAD;
        const bool inb = ((unsigned)gy < HNUM) & ((unsigned)gx < WNUM);
        const float* xb = xg + gy * WNUM + gx;
        float xi[IG];
        #pragma unroll
        for (int i = 0; i < IG; i++)
            xi[i] = inb ? __ldg(xb + i * PLANE) : 0.0f;
        #pragma unroll
        for (int c = 0; c < OGH; c++) {
            float kc = 0.0f, vc = 0.0f;
            #pragma unroll
            for (int i = 0; i < IG; i++) {
                const float2 w2 = wkv_s[c * IG + i];
                kc = fmaf(w2.x, xi[i], kc);
                vc = fmaf(w2.y, xi[i], vc);
            }
            *(float2*)&kv_s[c][yy][2 * xx] = make_float2(kc, vc);
        }
    }
    __syncthreads();

    // --- phase 2: attention; each thread owns 2 adjacent pixels, 4 channels ---
    const int tc = tid % TCN;
    const int y_ = tid / TCN;          // 0..15
    const int x_ = 2 * tc;
    const int gh = h0 + y_;
    const int gw = w0 + x_;

    const float LOG2E = 1.4426950408889634f;

    float qsv[OGH][2];
    {
        float xi0[IG], xi1[IG];
        const float* xb = xg + gh * WNUM + gw;
        #pragma unroll
        for (int i = 0; i < IG; i++) {
            float2 t = __ldg((const float2*)(xb + i * PLANE));
            xi0[i] = t.x; xi1[i] = t.y;
        }
        #pragma unroll
        for (int c = 0; c < OGH; c++) {
            float q0 = 0.0f, q1 = 0.0f;
            #pragma unroll
            for (int i = 0; i < IG; i++) {
                q0 = fmaf(wq_s[c * IG + i], xi0[i], q0);
                q1 = fmaf(wq_s[c * IG + i], xi1[i], q1);
            }
            qsv[c][0] = q0 * LOG2E;
            qsv[c][1] = q1 * LOG2E;
        }
    }

    float* op = out + ((size_t)(b * CIN + g * OG + cbase) * HNUM + gh) * WNUM + gw;

    if (half_ == 0) {
        // channels 0..3: emb varies along patch ROW (di)
        #pragma unroll 1
        for (int c = 0; c < OGH; c++) {
            const float qs0 = qsv[c][0], qs1 = qsv[c][1];
            float ssum0 = 0.0f, acc0 = 0.0f, ssum1 = 0.0f, acc1 = 0.0f;
            const float* kvp = &kv_s[c][y_][2 * x_];
            #pragma unroll
            for (int di = 0; di < KW; di++) {
                const float eh = emb_s[c * KW + di];
                const float qe0 = qs0 * eh, qe1 = qs1 * eh;
                const float4* rp = (const float4*)(kvp + di * KVSTR);
                float4 a0 = rp[0], a1 = rp[1], a2 = rp[2], a3 = rp[3];
                float kk[8] = {a0.x, a0.z, a1.x, a1.z, a2.x, a2.z, a3.x, a3.z};
                float vv[8] = {a0.y, a0.w, a1.y, a1.w, a2.y, a2.w, a3.y, a3.w};
                #pragma unroll
                for (int dj = 0; dj < KW; dj++) {
                    float e0 = ex2f(fmaf(qs0, kk[dj], qe0));
                    ssum0 += e0; acc0 = fmaf(e0, vv[dj], acc0);
                    float e1 = ex2f(fmaf(qs1, kk[dj + 1], qe1));
                    ssum1 += e1; acc1 = fmaf(e1, vv[dj + 1], acc1);
                }
            }
            *(float2*)&op[(size_t)c * PLANE] =
                make_float2(__fdividef(acc0, ssum0), __fdividef(acc1, ssum1));
        }
    } else {
        // channels 4..7: emb varies along patch COL (dj)
        #pragma unroll 1
        for (int c = 0; c < OGH; c++) {
            const float qs0 = qsv[c][0], qs1 = qsv[c][1];
            float qe0a[KW], qe1a[KW];
            #pragma unroll
            for (int t = 0; t < KW; t++) {
                const float ew = emb_s[c * KW + t];
                qe0a[t] = qs0 * ew;
                qe1a[t] = qs1 * ew;
            }
            float ssum0 = 0.0f, acc0 = 0.0f, ssum1 = 0.0f, acc1 = 0.0f;
            const float* kvp = &kv_s[c][y_][2 * x_];
            #pragma unroll
            for (int di = 0; di < KW; di++) {
                const float4* rp = (const float4*)(kvp + di * KVSTR);
                float4 a0 = rp[0], a1 = rp[1], a2 = rp[2], a3 = rp[3];
                float kk[8] = {a0.x, a0.z, a1.x, a1.z, a2.x, a2.z, a3.x, a3.z};
                float vv[8] = {a0.y, a0.w, a1.y, a1.w, a2.y, a2.w, a3.y, a3.w};
                #pragma unroll
                for (int dj = 0; dj < KW; dj++) {
                    float e0 = ex2f(fmaf(qs0, kk[dj], qe0a[dj]));
                    ssum0 += e0; acc0 = fmaf(e0, vv[dj], acc0);
                    float e1 = ex2f(fmaf(qs1, kk[dj + 1], qe1a[dj]));
                    ssum1 += e1; acc1 = fmaf(e1, vv[dj + 1], acc1);
                }
            }
            *(float2*)&op[(size_t)c * PLANE] =
                make_float2(__fdividef(acc0, ssum0), __fdividef(acc1, ssum1));
        }
    }
}

extern "C" void kernel_launch(void* const* d_in, const int* in_sizes, int n_in,
                              void* d_out, int out_size)
{
    const float* x     = (const float*)d_in[0];
    const float* wq    = (const float*)d_in[1];
    const float* wk    = (const float*)d_in[2];
    const float* wv    = (const float*)d_in[3];
    const float* h_emb = (const float*)d_in[4];
    const float* w_emb = (const float*)d_in[5];
    float* out = (float*)d_out;

    // (96/24) x (96/16) x 64 = 4 x 6 x 64 = 1536 blocks... wait: 4*6=24, *64 =
    // 1536. Capacity at 8 blocks/SM = 1184. Use TW=24,TH=16 -> grid.x=4,
    // grid.y=6 -> 24 tiles * 64 = 1536. Still 1.3 waves -> shrink z-split:
    // NO channel split would halve grid to 768 but double smem. Keep split;
    // 1536 blocks at 8/SM = 1.30 waves. Better: TH=16,TW=32 tile (16x16 thr
    // cols=256 thr) not 192. Compromise: accept 1536 with max occupancy.
    dim3 grid(WNUM / TW, HNUM / TH, BATCH * G * 2);  // (4, 6, 64) = 1536
    dim3 block(NTHREADS);
    attn_fused_kernel<<<grid, block>>>(x, wq, wk, wv, h_emb, w_emb, out);
}

// round 15
// speedup vs baseline: 1.0103x; 1.0103x over previous
#include <cuda_runtime.h>
#include <cuda_bf16.h>

// Problem constants (fixed shapes)
#define BATCH 4
#define CIN   64
#define HNUM  96
#define WNUM  96
#define G     8
#define OG    8
#define OGH   4            // channels handled per block
#define IG    8
#define KW    7
#define PAD   3
#define PLANE (HNUM * WNUM)

// Tiling: 192 threads = 12 rows x 16 thread-cols, 2 px per thread in w (R4).
#define TH 12
#define TW 32
#define TC 16
#define NTHREADS 192
#define HH (TH + KW - 1)    // 18
#define HWD (TW + KW - 1)   // 38
#define KVSTR 80            // floats per row: 38 px * 2 (k,v interleaved), pad 80

__device__ __forceinline__ float ex2f(float l) {
    float e;
    asm("ex2.approx.f32 %0, %1;" : "=f"(e) : "f"(l));
    return e;
}

// exp2 on the FMA/ALU pipes (no MUFU). Magic-constant range reduction.
// f in [-0.5,0.5], deg-4 poly, rel err <= ~4e-5.
__device__ __forceinline__ float exp2_poly(float l) {
    const float MAGIC = 12582912.0f;            // 1.5 * 2^23
    float t  = l + MAGIC;                       // FADD: rounds l to nearest int
    int   ni = __float_as_int(t) - 0x4B400000;  // integer(l), two's complement
    float f  = l - (t - MAGIC);                 // FADD, FADD: f in [-0.5, 0.5]
    float p = fmaf(f, 0.009618129f, 0.05550411f);
    p = fmaf(f, p, 0.2402265f);
    p = fmaf(f, p, 0.6931472f);
    p = fmaf(f, p, 1.0f);
    return __int_as_float(__float_as_int(p) + (ni << 23));
}

// Tap exp with compile-time pipe routing: POLY taps go to fma pipe.
template <bool POLY>
__device__ __forceinline__ float tap_exp(float l) {
    return POLY ? exp2_poly(l) : ex2f(l);
}

__global__ __launch_bounds__(NTHREADS)
void attn_fused_kernel(const float* __restrict__ x,
                       const float* __restrict__ wq,
                       const float* __restrict__ wk,
                       const float* __restrict__ wv,
                       const float* __restrict__ h_emb,
                       const float* __restrict__ w_emb,
                       float* __restrict__ out)
{
    // k,v interleaved per pixel for LDS.128: [ch][row][2*col + {k,v}]
    __shared__ __align__(16) float kv_s[OGH][HH][KVSTR];   // 4*18*80*4 = 22.5 KB
    __shared__ float  wq_s[OGH * IG];
    __shared__ float2 wkv_s[OGH * IG];                     // (wk, wv) pairs
    __shared__ float  emb_s[OGH * KW];                     // h_emb or w_emb slice

    const int tid  = threadIdx.x;
    const int bz   = blockIdx.z;       // ((b*8+g)*2 + half)
    const int half = bz & 1;
    const int g    = (bz >> 1) & 7;
    const int b    = bz >> 4;
    const int h0   = blockIdx.y * TH;
    const int w0   = blockIdx.x * TW;

    // --- per-block weights + embeddings (4 channels worth) ---
    if (tid < 32) {
        const int wi = g * 64 + half * 32 + tid;
        wq_s[tid]  = wq[wi];
        wkv_s[tid] = make_float2(wk[wi], wv[wi]);
    } else if (tid >= 32 && tid < 60) {
        const float* ep = half ? w_emb : h_emb;
        emb_s[tid - 32] = ep[g * 28 + (tid - 32)];
    }
    __syncthreads();

    const float* xg = x + (size_t)(b * CIN + g * IG) * PLANE;
    const int cbase = half * OGH;      // first global channel of this block

    // --- phase 1: grouped 1x1 conv k,v over haloed tile -> interleaved SMEM ---
    for (int p = tid; p < HH * HWD; p += NTHREADS) {
        const int yy = p / HWD;
        const int xx = p - yy * HWD;
        const int gy = h0 + yy - PAD;
        const int gx = w0 + xx - PAD;
        const bool inb = ((unsigned)gy < HNUM) & ((unsigned)gx < WNUM);
        const float* xb = xg + gy * WNUM + gx;
        float xi[IG];
        #pragma unroll
        for (int i = 0; i < IG; i++)
            xi[i] = inb ? __ldg(xb + i * PLANE) : 0.0f;
        #pragma unroll
        for (int c = 0; c < OGH; c++) {
            float kc = 0.0f, vc = 0.0f;
            #pragma unroll
            for (int i = 0; i < IG; i++) {
                const float2 w2 = wkv_s[c * IG + i];
                kc = fmaf(w2.x, xi[i], kc);
                vc = fmaf(w2.y, xi[i], vc);
            }
            *(float2*)&kv_s[c][yy][2 * xx] = make_float2(kc, vc);
        }
    }
    __syncthreads();

    // --- phase 2: attention; each thread owns 2 adjacent pixels, 4 channels ---
    const int tc = tid & (TC - 1);
    const int y_ = tid >> 4;
    const int x_ = 2 * tc;
    const int gh = h0 + y_;
    const int gw = w0 + x_;

    float xi0[IG], xi1[IG];
    {
        const float* xb = xg + gh * WNUM + gw;
        #pragma unroll
        for (int i = 0; i < IG; i++) {
            float2 t = __ldg((const float2*)(xb + i * PLANE));
            xi0[i] = t.x; xi1[i] = t.y;
        }
    }

    float* op = out + ((size_t)(b * CIN + g * OG + cbase) * HNUM + gh) * WNUM + gw;

    const float LOG2E = 1.4426950408889634f;

    if (half == 0) {
        // channels 0..3: emb varies along patch ROW (di)
        #pragma unroll 1
        for (int c = 0; c < OGH; c++) {
            float qs0 = 0.0f, qs1 = 0.0f;
            #pragma unroll
            for (int i = 0; i < IG; i++) {
                qs0 = fmaf(wq_s[c * IG + i], xi0[i], qs0);
                qs1 = fmaf(wq_s[c * IG + i], xi1[i], qs1);
            }
            qs0 *= LOG2E; qs1 *= LOG2E;

            float ssum0 = 0.0f, acc0 = 0.0f, ssum1 = 0.0f, acc1 = 0.0f;
            #pragma unroll
            for (int di = 0; di < KW; di++) {
                const float eh = emb_s[c * KW + di];
                const float qe0 = qs0 * eh, qe1 = qs1 * eh;
                const float4* rp = (const float4*)&kv_s[c][y_ + di][2 * x_];
                float4 a0 = rp[0], a1 = rp[1], a2 = rp[2], a3 = rp[3];
                float kk[8] = {a0.x, a0.z, a1.x, a1.z, a2.x, a2.z, a3.x, a3.z};
                float vv[8] = {a0.y, a0.w, a1.y, a1.w, a2.y, a2.w, a3.y, a3.w};
                #pragma unroll
                for (int dj = 0; dj < KW; dj++) {
                    // pipe routing: px0 poly at dj==3; px1 poly at dj==3, odd di
                    const float l0 = fmaf(qs0, kk[dj], qe0);
                    float e0 = (dj == 3) ? tap_exp<true>(l0) : tap_exp<false>(l0);
                    ssum0 += e0; acc0 = fmaf(e0, vv[dj], acc0);
                    const float l1 = fmaf(qs1, kk[dj + 1], qe1);
                    float e1 = (dj == 3 && (di & 1)) ? tap_exp<true>(l1)
                                                     : tap_exp<false>(l1);
                    ssum1 += e1; acc1 = fmaf(e1, vv[dj + 1], acc1);
                }
            }
            float2 o = make_float2(__fdividef(acc0, ssum0), __fdividef(acc1, ssum1));
            *(float2*)&op[(size_t)c * PLANE] = o;
        }
    } else {
        // channels 4..7: emb varies along patch COL (dj)
        #pragma unroll 1
        for (int c = 0; c < OGH; c++) {
            float qs0 = 0.0f, qs1 = 0.0f;
            #pragma unroll
            for (int i = 0; i < IG; i++) {
                qs0 = fmaf(wq_s[c * IG + i], xi0[i], qs0);
                qs1 = fmaf(wq_s[c * IG + i], xi1[i], qs1);
            }
            qs0 *= LOG2E; qs1 *= LOG2E;

            float qe0a[KW], qe1a[KW];
            #pragma unroll
            for (int t = 0; t < KW; t++) {
                const float ew = emb_s[c * KW + t];
                qe0a[t] = qs0 * ew;
                qe1a[t] = qs1 * ew;
            }

            float ssum0 = 0.0f, acc0 = 0.0f, ssum1 = 0.0f, acc1 = 0.0f;
            #pragma unroll
            for (int di = 0; di < KW; di++) {
                const float4* rp = (const float4*)&kv_s[c][y_ + di][2 * x_];
                float4 a0 = rp[0], a1 = rp[1], a2 = rp[2], a3 = rp[3];
                float kk[8] = {a0.x, a0.z, a1.x, a1.z, a2.x, a2.z, a3.x, a3.z};
                float vv[8] = {a0.y, a0.w, a1.y, a1.w, a2.y, a2.w, a3.y, a3.w};
                #pragma unroll
                for (int dj = 0; dj < KW; dj++) {
                    const float l0 = fmaf(qs0, kk[dj], qe0a[dj]);
                    float e0 = (dj == 3) ? tap_exp<true>(l0) : tap_exp<false>(l0);
                    ssum0 += e0; acc0 = fmaf(e0, vv[dj], acc0);
                    const float l1 = fmaf(qs1, kk[dj + 1], qe1a[dj]);
                    float e1 = (dj == 3 && (di & 1)) ? tap_exp<true>(l1)
                                                     : tap_exp<false>(l1);
                    ssum1 += e1; acc1 = fmaf(e1, vv[dj + 1], acc1);
                }
            }
            float2 o = make_float2(__fdividef(acc0, ssum0), __fdividef(acc1, ssum1));
            *(float2*)&op[(size_t)c * PLANE] = o;
        }
    }
}

extern "C" void kernel_launch(void* const* d_in, const int* in_sizes, int n_in,
                              void* d_out, int out_size)
{
    const float* x     = (const float*)d_in[0];
    const float* wq    = (const float*)d_in[1];
    const float* wk    = (const float*)d_in[2];
    const float* wv    = (const float*)d_in[3];
    const float* h_emb = (const float*)d_in[4];
    const float* w_emb = (const float*)d_in[5];
    float* out = (float*)d_out;

    dim3 grid(WNUM / TW, HNUM / TH, BATCH * G * 2);  // (3, 8, 64) = 1536 blocks
    dim3 block(NTHREADS);
    attn_fused_kernel<<<grid, block>>>(x, wq, wk, wv, h_emb, w_emb, out);
}

// round 16
// speedup vs baseline: 1.0447x; 1.0341x over previous
#include <cuda_runtime.h>
#include <cuda_bf16.h>

// Problem constants (fixed shapes)
#define BATCH 4
#define CIN   64
#define HNUM  96
#define WNUM  96
#define G     8
#define OG    8
#define OGH   4            // channels handled per block
#define IG    8
#define KW    7
#define PAD   3
#define PLANE (HNUM * WNUM)

// Tiling: 192 threads = 12 rows x 16 thread-cols, 2 px per thread in w (R4).
#define TH 12
#define TW 32
#define TC 16
#define NTHREADS 192
#define HH (TH + KW - 1)    // 18
#define HWD (TW + KW - 1)   // 38
#define KVSTR 80            // floats per row: 38 px * 2 (k,v interleaved), pad 80

__device__ __forceinline__ float ex2f(float l) {
    float e;
    asm("ex2.approx.f32 %0, %1;" : "=f"(e) : "f"(l));
    return e;
}

// exp2 on FMA pipe only (~7-8 SASS ops, no MUFU). Magic-add range reduction,
// deg-3 poly on f in [-0.5,0.5]; rel err <= ~6e-4 (Taylor tail). Used on 4%
// of taps -> aggregate output error ~2e-5, negligible.
__device__ __forceinline__ float exp2_fma(float l) {
    const float MAGIC = 12582912.0f;            // 1.5 * 2^23
    float t = l + MAGIC;                        // low 23 bits of t = round(l)
    float u = t - MAGIC;                        // u = round(l)
    float f = l - u;                            // f in [-0.5, 0.5]
    float p = fmaf(f, 0.05550411f, 0.24022651f);
    p = fmaf(f, p, 0.69314718f);
    p = fmaf(f, p, 1.0f);
    // splice exponent: (bits(t) << 23) == n << 23 exactly (upper bits wrap out)
    unsigned nsh = ((unsigned)__float_as_int(t)) << 23;
    return __int_as_float((int)((unsigned)__float_as_int(p) + nsh));
}

__global__ __launch_bounds__(NTHREADS)
void attn_fused_kernel(const float* __restrict__ x,
                       const float* __restrict__ wq,
                       const float* __restrict__ wk,
                       const float* __restrict__ wv,
                       const float* __restrict__ h_emb,
                       const float* __restrict__ w_emb,
                       float* __restrict__ out)
{
    // k,v interleaved per pixel for LDS.128: [ch][row][2*col + {k,v}]
    __shared__ __align__(16) float kv_s[OGH][HH][KVSTR];   // 4*18*80*4 = 22.5 KB
    __shared__ float  wq_s[OGH * IG];
    __shared__ float2 wkv_s[OGH * IG];                     // (wk, wv) pairs
    __shared__ float  emb_s[OGH * KW];                     // h_emb or w_emb slice

    const int tid  = threadIdx.x;
    const int bz   = blockIdx.z;       // ((b*8+g)*2 + half)
    const int half = bz & 1;
    const int g    = (bz >> 1) & 7;
    const int b    = bz >> 4;
    const int h0   = blockIdx.y * TH;
    const int w0   = blockIdx.x * TW;

    // --- per-block weights + embeddings (4 channels worth) ---
    if (tid < 32) {
        const int wi = g * 64 + half * 32 + tid;
        wq_s[tid]  = wq[wi];
        wkv_s[tid] = make_float2(wk[wi], wv[wi]);
    } else if (tid >= 32 && tid < 60) {
        const float* ep = half ? w_emb : h_emb;
        emb_s[tid - 32] = ep[g * 28 + (tid - 32)];
    }
    __syncthreads();

    const float* xg = x + (size_t)(b * CIN + g * IG) * PLANE;
    const int cbase = half * OGH;      // first global channel of this block

    // --- phase 1: grouped 1x1 conv k,v over haloed tile -> interleaved SMEM ---
    for (int p = tid; p < HH * HWD; p += NTHREADS) {
        const int yy = p / HWD;
        const int xx = p - yy * HWD;
        const int gy = h0 + yy - PAD;
        const int gx = w0 + xx - PAD;
        const bool inb = ((unsigned)gy < HNUM) & ((unsigned)gx < WNUM);
        const float* xb = xg + gy * WNUM + gx;
        float xi[IG];
        #pragma unroll
        for (int i = 0; i < IG; i++)
            xi[i] = inb ? __ldg(xb + i * PLANE) : 0.0f;
        #pragma unroll
        for (int c = 0; c < OGH; c++) {
            float kc = 0.0f, vc = 0.0f;
            #pragma unroll
            for (int i = 0; i < IG; i++) {
                const float2 w2 = wkv_s[c * IG + i];
                kc = fmaf(w2.x, xi[i], kc);
                vc = fmaf(w2.y, xi[i], vc);
            }
            *(float2*)&kv_s[c][yy][2 * xx] = make_float2(kc, vc);
        }
    }
    __syncthreads();

    // --- phase 2: attention; each thread owns 2 adjacent pixels, 4 channels ---
    const int tc = tid & (TC - 1);
    const int y_ = tid >> 4;
    const int x_ = 2 * tc;
    const int gh = h0 + y_;
    const int gw = w0 + x_;

    float xi0[IG], xi1[IG];
    {
        const float* xb = xg + gh * WNUM + gw;
        #pragma unroll
        for (int i = 0; i < IG; i++) {
            float2 t = __ldg((const float2*)(xb + i * PLANE));
            xi0[i] = t.x; xi1[i] = t.y;
        }
    }

    float* op = out + ((size_t)(b * CIN + g * OG + cbase) * HNUM + gh) * WNUM + gw;

    const float LOG2E = 1.4426950408889634f;

    if (half == 0) {
        // channels 0..3: emb varies along patch ROW (di)
        #pragma unroll 1
        for (int c = 0; c < OGH; c++) {
            float qs0 = 0.0f, qs1 = 0.0f;
            #pragma unroll
            for (int i = 0; i < IG; i++) {
                qs0 = fmaf(wq_s[c * IG + i], xi0[i], qs0);
                qs1 = fmaf(wq_s[c * IG + i], xi1[i], qs1);
            }
            qs0 *= LOG2E; qs1 *= LOG2E;

            float ssum0 = 0.0f, acc0 = 0.0f, ssum1 = 0.0f, acc1 = 0.0f;
            #pragma unroll
            for (int di = 0; di < KW; di++) {
                const float eh = emb_s[c * KW + di];
                const float qe0 = qs0 * eh, qe1 = qs1 * eh;
                const float4* rp = (const float4*)&kv_s[c][y_ + di][2 * x_];
                float4 a0 = rp[0], a1 = rp[1], a2 = rp[2], a3 = rp[3];
                float kk[8] = {a0.x, a0.z, a1.x, a1.z, a2.x, a2.z, a3.x, a3.z};
                float vv[8] = {a0.y, a0.w, a1.y, a1.w, a2.y, a2.w, a3.y, a3.w};
                #pragma unroll
                for (int dj = 0; dj < KW; dj++) {
                    // balanced offload: px0 tap (dj==3, even di) -> FMA-pipe exp
                    const float l0 = fmaf(qs0, kk[dj], qe0);
                    float e0 = (dj == 3 && (di & 1) == 0) ? exp2_fma(l0) : ex2f(l0);
                    ssum0 += e0; acc0 = fmaf(e0, vv[dj], acc0);
                    const float l1 = fmaf(qs1, kk[dj + 1], qe1);
                    float e1 = ex2f(l1);
                    ssum1 += e1; acc1 = fmaf(e1, vv[dj + 1], acc1);
                }
            }
            float2 o = make_float2(__fdividef(acc0, ssum0), __fdividef(acc1, ssum1));
            *(float2*)&op[(size_t)c * PLANE] = o;
        }
    } else {
        // channels 4..7: emb varies along patch COL (dj)
        #pragma unroll 1
        for (int c = 0; c < OGH; c++) {
            float qs0 = 0.0f, qs1 = 0.0f;
            #pragma unroll
            for (int i = 0; i < IG; i++) {
                qs0 = fmaf(wq_s[c * IG + i], xi0[i], qs0);
                qs1 = fmaf(wq_s[c * IG + i], xi1[i], qs1);
            }
            qs0 *= LOG2E; qs1 *= LOG2E;

            float qe0a[KW], qe1a[KW];
            #pragma unroll
            for (int t = 0; t < KW; t++) {
                const float ew = emb_s[c * KW + t];
                qe0a[t] = qs0 * ew;
                qe1a[t] = qs1 * ew;
            }

            float ssum0 = 0.0f, acc0 = 0.0f, ssum1 = 0.0f, acc1 = 0.0f;
            #pragma unroll
            for (int di = 0; di < KW; di++) {
                const float4* rp = (const float4*)&kv_s[c][y_ + di][2 * x_];
                float4 a0 = rp[0], a1 = rp[1], a2 = rp[2], a3 = rp[3];
                float kk[8] = {a0.x, a0.z, a1.x, a1.z, a2.x, a2.z, a3.x, a3.z};
                float vv[8] = {a0.y, a0.w, a1.y, a1.w, a2.y, a2.w, a3.y, a3.w};
                #pragma unroll
                for (int dj = 0; dj < KW; dj++) {
                    const float l0 = fmaf(qs0, kk[dj], qe0a[dj]);
                    float e0 = (dj == 3 && (di & 1) == 0) ? exp2_fma(l0) : ex2f(l0);
                    ssum0 += e0; acc0 = fmaf(e0, vv[dj], acc0);
                    const float l1 = fmaf(qs1, kk[dj + 1], qe1a[dj]);
                    float e1 = ex2f(l1);
                    ssum1 += e1; acc1 = fmaf(e1, vv[dj + 1], acc1);
                }
            }
            float2 o = make_float2(__fdividef(acc0, ssum0), __fdividef(acc1, ssum1));
            *(float2*)&op[(size_t)c * PLANE] = o;
        }
    }
}

extern "C" void kernel_launch(void* const* d_in, const int* in_sizes, int n_in,
                              void* d_out, int out_size)
{
    const float* x     = (const float*)d_in[0];
    const float* wq    = (const float*)d_in[1];
    const float* wk    = (const float*)d_in[2];
    const float* wv    = (const float*)d_in[3];
    const float* h_emb = (const float*)d_in[4];
    const float* w_emb = (const float*)d_in[5];
    float* out = (float*)d_out;

    dim3 grid(WNUM / TW, HNUM / TH, BATCH * G * 2);  // (3, 8, 64) = 1536 blocks
    dim3 block(NTHREADS);
    attn_fused_kernel<<<grid, block>>>(x, wq, wk, wv, h_emb, w_emb, out);
}

// round 17
// speedup vs baseline: 1.1473x; 1.0982x over previous
#include <cuda_runtime.h>
#include <cuda_bf16.h>

// Problem constants (fixed shapes)
#define BATCH 4
#define CIN   64
#define HNUM  96
#define WNUM  96
#define G     8
#define OG    8
#define OGH   4            // channels handled per block
#define IG    8
#define KW    7
#define PAD   3
#define PLANE (HNUM * WNUM)

// Tiling: 256 threads = 16 rows x 16 thread-cols, 2 px per thread in w.
// Halo ratio 1.63 (vs 1.78 at 12x32) -> ~8% less conv work.
#define TH 16
#define TW 32
#define TC 16
#define NTHREADS 256
#define HH (TH + KW - 1)    // 22
#define HWD (TW + KW - 1)   // 38
#define KVSTR 80            // floats per row: 38 px * 2 (k,v interleaved), pad 80

__device__ __forceinline__ float ex2f(float l) {
    float e;
    asm("ex2.approx.f32 %0, %1;" : "=f"(e) : "f"(l));
    return e;
}

__global__ __launch_bounds__(NTHREADS)
void attn_fused_kernel(const float* __restrict__ x,
                       const float* __restrict__ wq,
                       const float* __restrict__ wk,
                       const float* __restrict__ wv,
                       const float* __restrict__ h_emb,
                       const float* __restrict__ w_emb,
                       float* __restrict__ out)
{
    // k,v interleaved per pixel for LDS.128: [ch][row][2*col + {k,v}]
    __shared__ __align__(16) float kv_s[OGH][HH][KVSTR];   // 4*22*80*4 = 28.2 KB
    __shared__ float  wq_s[OGH * IG];
    __shared__ float2 wkv_s[OGH * IG];                     // (wk, wv) pairs
    __shared__ float  emb_s[OGH * KW];                     // h_emb or w_emb slice

    const int tid  = threadIdx.x;
    const int bz   = blockIdx.z;       // ((b*8+g)*2 + half)
    const int half = bz & 1;
    const int g    = (bz >> 1) & 7;
    const int b    = bz >> 4;
    const int h0   = blockIdx.y * TH;
    const int w0   = blockIdx.x * TW;

    // --- per-block weights + embeddings (4 channels worth) ---
    if (tid < 32) {
        const int wi = g * 64 + half * 32 + tid;
        wq_s[tid]  = wq[wi];
        wkv_s[tid] = make_float2(wk[wi], wv[wi]);
    } else if (tid >= 32 && tid < 60) {
        const float* ep = half ? w_emb : h_emb;
        emb_s[tid - 32] = ep[g * 28 + (tid - 32)];
    }
    __syncthreads();

    const float* xg = x + (size_t)(b * CIN + g * IG) * PLANE;
    const int cbase = half * OGH;      // first global channel of this block

    // --- phase 1: grouped 1x1 conv k,v over haloed tile -> interleaved SMEM ---
    for (int p = tid; p < HH * HWD; p += NTHREADS) {
        const int yy = p / HWD;
        const int xx = p - yy * HWD;
        const int gy = h0 + yy - PAD;
        const int gx = w0 + xx - PAD;
        const bool inb = ((unsigned)gy < HNUM) & ((unsigned)gx < WNUM);
        const float* xb = xg + gy * WNUM + gx;
        float xi[IG];
        #pragma unroll
        for (int i = 0; i < IG; i++)
            xi[i] = inb ? __ldg(xb + i * PLANE) : 0.0f;
        #pragma unroll
        for (int c = 0; c < OGH; c++) {
            float kc = 0.0f, vc = 0.0f;
            #pragma unroll
            for (int i = 0; i < IG; i++) {
                const float2 w2 = wkv_s[c * IG + i];
                kc = fmaf(w2.x, xi[i], kc);
                vc = fmaf(w2.y, xi[i], vc);
            }
            *(float2*)&kv_s[c][yy][2 * xx] = make_float2(kc, vc);
        }
    }
    __syncthreads();

    // --- phase 2: attention; each thread owns 2 adjacent pixels, 4 channels ---
    const int tc = tid & (TC - 1);
    const int y_ = tid >> 4;           // 0..15
    const int x_ = 2 * tc;
    const int gh = h0 + y_;
    const int gw = w0 + x_;

    float xi0[IG], xi1[IG];
    {
        const float* xb = xg + gh * WNUM + gw;
        #pragma unroll
        for (int i = 0; i < IG; i++) {
            float2 t = __ldg((const float2*)(xb + i * PLANE));
            xi0[i] = t.x; xi1[i] = t.y;
        }
    }

    float* op = out + ((size_t)(b * CIN + g * OG + cbase) * HNUM + gh) * WNUM + gw;

    const float LOG2E = 1.4426950408889634f;

    if (half == 0) {
        // channels 0..3: emb varies along patch ROW (di)
        #pragma unroll 1
        for (int c = 0; c < OGH; c++) {
            float qs0 = 0.0f, qs1 = 0.0f;
            #pragma unroll
            for (int i = 0; i < IG; i++) {
                qs0 = fmaf(wq_s[c * IG + i], xi0[i], qs0);
                qs1 = fmaf(wq_s[c * IG + i], xi1[i], qs1);
            }
            qs0 *= LOG2E; qs1 *= LOG2E;

            float ssum0 = 0.0f, acc0 = 0.0f, ssum1 = 0.0f, acc1 = 0.0f;
            #pragma unroll
            for (int di = 0; di < KW; di++) {
                const float eh = emb_s[c * KW + di];
                const float qe0 = qs0 * eh, qe1 = qs1 * eh;
                const float4* rp = (const float4*)&kv_s[c][y_ + di][2 * x_];
                float4 a0 = rp[0], a1 = rp[1], a2 = rp[2], a3 = rp[3];
                float kk[8] = {a0.x, a0.z, a1.x, a1.z, a2.x, a2.z, a3.x, a3.z};
                float vv[8] = {a0.y, a0.w, a1.y, a1.w, a2.y, a2.w, a3.y, a3.w};
                #pragma unroll
                for (int dj = 0; dj < KW; dj++) {
                    float e0 = ex2f(fmaf(qs0, kk[dj], qe0));
                    ssum0 += e0; acc0 = fmaf(e0, vv[dj], acc0);
                    float e1 = ex2f(fmaf(qs1, kk[dj + 1], qe1));
                    ssum1 += e1; acc1 = fmaf(e1, vv[dj + 1], acc1);
                }
            }
            float2 o = make_float2(__fdividef(acc0, ssum0), __fdividef(acc1, ssum1));
            *(float2*)&op[(size_t)c * PLANE] = o;
        }
    } else {
        // channels 4..7: emb varies along patch COL (dj)
        #pragma unroll 1
        for (int c = 0; c < OGH; c++) {
            float qs0 = 0.0f, qs1 = 0.0f;
            #pragma unroll
            for (int i = 0; i < IG; i++) {
                qs0 = fmaf(wq_s[c * IG + i], xi0[i], qs0);
                qs1 = fmaf(wq_s[c * IG + i], xi1[i], qs1);
            }
            qs0 *= LOG2E; qs1 *= LOG2E;

            float qe0a[KW], qe1a[KW];
            #pragma unroll
            for (int t = 0; t < KW; t++) {
                const float ew = emb_s[c * KW + t];
                qe0a[t] = qs0 * ew;
                qe1a[t] = qs1 * ew;
            }

            float ssum0 = 0.0f, acc0 = 0.0f, ssum1 = 0.0f, acc1 = 0.0f;
            #pragma unroll
            for (int di = 0; di < KW; di++) {
                const float4* rp = (const float4*)&kv_s[c][y_ + di][2 * x_];
                float4 a0 = rp[0], a1 = rp[1], a2 = rp[2], a3 = rp[3];
                float kk[8] = {a0.x, a0.z, a1.x, a1.z, a2.x, a2.z, a3.x, a3.z};
                float vv[8] = {a0.y, a0.w, a1.y, a1.w, a2.y, a2.w, a3.y, a3.w};
                #pragma unroll
                for (int dj = 0; dj < KW; dj++) {
                    float e0 = ex2f(fmaf(qs0, kk[dj], qe0a[dj]));
                    ssum0 += e0; acc0 = fmaf(e0, vv[dj], acc0);
                    float e1 = ex2f(fmaf(qs1, kk[dj + 1], qe1a[dj]));
                    ssum1 += e1; acc1 = fmaf(e1, vv[dj + 1], acc1);
                }
            }
            float2 o = make_float2(__fdividef(acc0, ssum0), __fdividef(acc1, ssum1));
            *(float2*)&op[(size_t)c * PLANE] = o;
        }
    }
}

extern "C" void kernel_launch(void* const* d_in, const int* in_sizes, int n_in,
                              void* d_out, int out_size)
{
    const float* x     = (const float*)d_in[0];
    const float* wq    = (const float*)d_in[1];
    const float* wk    = (const float*)d_in[2];
    const float* wv    = (const float*)d_in[3];
    const float* h_emb = (const float*)d_in[4];
    const float* w_emb = (const float*)d_in[5];
    float* out = (float*)d_out;

    dim3 grid(WNUM / TW, HNUM / TH, BATCH * G * 2);  // (3, 6, 64) = 1152 blocks
    dim3 block(NTHREADS);
    attn_fused_kernel<<<grid, block>>>(x, wq, wk, wv, h_emb, w_emb, out);
}